// round 17
// baseline (speedup 1.0000x reference)
#include <cuda_runtime.h>
#include <cstdint>

#define DIM 64
#define KCODES 1024
#define NROWS (32*64*64)
#define QELEMS (NROWS*DIM)
#define NSM 148
#define NUNITS 1024

__device__ float2 g_ef[KCODES];        // (se_exact, 2*scale_e)
__device__ int    g_e8T[16][KCODES];   // packed 4-chan groups, [i][code]
__device__ unsigned g_stats[2];        // SEC_MAX, SE_MAX (float bits, >=0)
__device__ uint4  g_x8[NROWS];         // x int8 groups 0..3
__device__ uint4  g_x8b[NROWS][3];     // groups 4..15
__device__ float4 g_xf[NROWS];         // {scale_x, B_row, sx, 0}
__device__ uint4  g_q[4][NROWS];       // top4 packed per quarter
__device__ float  g_losspart[512];
__device__ int    g_ctr;

__device__ __forceinline__ uint32_t s2u(const void* p){
    uint32_t a; asm("{ .reg .u64 t; cvta.to.shared.u64 t, %1; cvt.u32.u64 %0, t; }":"=r"(a):"l"(p)); return a;
}
#define CPA16(dst, src) asm volatile("cp.async.cg.shared.global [%0], [%1], 16;"::"r"(dst),"l"(src):"memory")
#define CPCOMMIT()      asm volatile("cp.async.commit_group;":::"memory")
#define CPWAIT(n)       asm volatile("cp.async.wait_group %0;"::"n"(n):"memory")

__device__ __forceinline__ uint32_t packdk(float d, int k) {
    uint32_t b = __float_as_uint(d);
    uint32_t u = (b & 0x80000000u) ? ~b : (b | 0x80000000u);
    return (u & 0xFFFFFC00u) | (uint32_t)k;
}
__device__ __forceinline__ float unpd(uint32_t p) {
    uint32_t u = p & 0xFFFFFC00u;
    uint32_t b = (u & 0x80000000u) ? (u & 0x7FFFFFFFu) : ~u;
    return __uint_as_float(b);
}
__device__ __forceinline__ void ins4(uint32_t* t, uint32_t p) {
    if (p < t[3]) {
        if (p < t[1]) {
            t[3] = t[2]; t[2] = t[1];
            if (p < t[0]) { t[1] = t[0]; t[0] = p; } else t[1] = p;
        } else {
            if (p < t[2]) { t[3] = t[2]; t[2] = p; } else t[3] = p;
        }
    }
}
__device__ __forceinline__ int q8(float v, float inv) {
    int r = __float2int_rn(v * inv);
    return max(-127, min(127, r));
}
__device__ __forceinline__ unsigned pk4(int a, int b, int c, int d) {
    return (unsigned)(a & 0xFF) | ((unsigned)(b & 0xFF) << 8) |
           ((unsigned)(c & 0xFF) << 16) | ((unsigned)(d & 0xFF) << 24);
}

// ---------- prep: codebook stats + int8 transpose + ctr --------------------
__global__ void vq_prep(const float* __restrict__ cb) {
    int k = blockIdx.x * blockDim.x + threadIdx.x;
    if (k == 0) g_ctr = NSM;
    if (k >= KCODES) return;
    const float* e = cb + k * DIM;
    float se = 0.f, maxe = 0.f, sume = 0.f;
#pragma unroll
    for (int c = 0; c < DIM; ++c) {
        float v = e[c];
        se = fmaf(v, v, se);              // exact-chain se (bit-matches R2 usage)
        maxe = fmaxf(maxe, fabsf(v));
        sume += fabsf(v);
    }
    float sce = (maxe > 0.f) ? maxe / 127.0f : 1.0f;
    float inv = 127.0f / fmaxf(maxe, 1e-30f);
#pragma unroll
    for (int i = 0; i < 16; ++i)
        g_e8T[i][k] = pk4(q8(e[4*i], inv), q8(e[4*i+1], inv),
                          q8(e[4*i+2], inv), q8(e[4*i+3], inv));
    g_ef[k] = make_float2(se, 2.0f * sce);
    atomicMax(&g_stats[0], __float_as_uint(sce));
    atomicMax(&g_stats[1], __float_as_uint(sume));
}

// ---------- xq: quantize x rows, per-row stats -----------------------------
__global__ __launch_bounds__(128) void vq_xq(const float* __restrict__ x) {
    __shared__ float xs[128 * 65];
    const int tid = threadIdx.x;
    const int n0 = blockIdx.x * 128;
    const int b = n0 >> 12, off = n0 & 4095;
    const float* xb = x + (size_t)b*262144 + off;
    for (int i = tid; i < 2048; i += 128) {
        int c = i >> 5, r4 = (i & 31) << 2;
        float4 v = *reinterpret_cast<const float4*>(xb + c*4096 + r4);
        xs[(r4+0)*65 + c] = v.x; xs[(r4+1)*65 + c] = v.y;
        xs[(r4+2)*65 + c] = v.z; xs[(r4+3)*65 + c] = v.w;
    }
    __syncthreads();
    const float* xr = xs + tid * 65;
    float maxx = 0.f, sumx = 0.f, sx = 0.f;
#pragma unroll
    for (int c = 0; c < DIM; ++c) {
        float v = xr[c];
        sx = fmaf(v, v, sx);
        float a = fabsf(v);
        maxx = fmaxf(maxx, a); sumx += a;
    }
    float scale = (maxx > 0.f) ? maxx / 127.0f : 1.0f;
    float inv = 127.0f / fmaxf(maxx, 1e-30f);
    int n = n0 + tid;
    uint4 w0, wv;
    w0 = make_uint4(pk4(q8(xr[0],inv),q8(xr[1],inv),q8(xr[2],inv),q8(xr[3],inv)),
                    pk4(q8(xr[4],inv),q8(xr[5],inv),q8(xr[6],inv),q8(xr[7],inv)),
                    pk4(q8(xr[8],inv),q8(xr[9],inv),q8(xr[10],inv),q8(xr[11],inv)),
                    pk4(q8(xr[12],inv),q8(xr[13],inv),q8(xr[14],inv),q8(xr[15],inv)));
    g_x8[n] = w0;
#pragma unroll
    for (int s = 0; s < 3; ++s) {
        const float* p = xr + 16 + s*16;
        wv = make_uint4(pk4(q8(p[0],inv),q8(p[1],inv),q8(p[2],inv),q8(p[3],inv)),
                        pk4(q8(p[4],inv),q8(p[5],inv),q8(p[6],inv),q8(p[7],inv)),
                        pk4(q8(p[8],inv),q8(p[9],inv),q8(p[10],inv),q8(p[11],inv)),
                        pk4(q8(p[12],inv),q8(p[13],inv),q8(p[14],inv),q8(p[15],inv)));
        g_x8b[n][s] = wv;
    }
    float SEC = __uint_as_float(g_stats[0]);
    float SE  = __uint_as_float(g_stats[1]);
    float B = 2.0f * (SEC * (sumx + 32.0f*scale) + scale * SE) * 1.1f + 1e-4f;
    g_xf[n] = make_float4(scale, B, sx, 0.f);
}

// ---------- main: persistent dp4a scan -------------------------------------
__global__ __launch_bounds__(128, 1) void vq_main() {
    __shared__ int es[16][256];
    __shared__ float2 ef[256];
    __shared__ int ms[1];
    const int tid = threadIdx.x;
    const uint32_t es_a = s2u(&es[0][0]);
    const uint32_t ef_a = s2u(&ef[0]);

    int u = blockIdx.x;
    while (u < NUNITS) {
        const int tile = u >> 2, q = u & 3;
        const int n0 = tile * 512;

        // e8 quarter + ef via cp.async
        for (int j = tid; j < 1024; j += 128) {
            int i = j >> 6, w = j & 63;
            CPA16(es_a + (i*256 + w*4)*4, (const void*)&g_e8T[i][q*256 + w*4]);
        }
        CPA16(ef_a + tid*16, (const void*)&g_ef[q*256 + tid*2]);
        CPCOMMIT();

        // x8 + scale into registers (4 rows/thread)
        int xi[4][16]; float xsc[4]; int rown[4];
#pragma unroll
        for (int j = 0; j < 4; ++j) {
            int r = n0 + tid + j*128;
            rown[j] = r;
            uint4 v0 = g_x8[r];
            xi[j][0]=v0.x; xi[j][1]=v0.y; xi[j][2]=v0.z; xi[j][3]=v0.w;
#pragma unroll
            for (int s = 0; s < 3; ++s) {
                uint4 v = g_x8b[r][s];
                xi[j][4+s*4]=v.x; xi[j][5+s*4]=v.y; xi[j][6+s*4]=v.z; xi[j][7+s*4]=v.w;
            }
            xsc[j] = g_xf[r].x;
        }
        CPWAIT(0);
        __syncthreads();

        // FIX R16: valid finite sentinel (old 0xFFFFFFFF decoded to NaN and
        // froze the tracker after one insert -> garbage candidates everywhere)
        const uint32_t SENT = packdk(3.0e38f, 1023);
        uint32_t t[4][4]; float t3f[4];
#pragma unroll
        for (int j = 0; j < 4; ++j) {
            t[j][0]=t[j][1]=t[j][2]=t[j][3]=SENT;
            t3f[j] = 3.0e38f;
        }

#pragma unroll 1
        for (int c8 = 0; c8 < 32; ++c8) {
            int acc[4][8];
#pragma unroll
            for (int j = 0; j < 4; ++j)
#pragma unroll
                for (int p = 0; p < 8; ++p) acc[j][p] = 0;
#pragma unroll 4
            for (int i = 0; i < 16; ++i) {
                int4 ea = *reinterpret_cast<const int4*>(&es[i][c8*8]);     // bcast
                int4 eb = *reinterpret_cast<const int4*>(&es[i][c8*8+4]);
#pragma unroll
                for (int j = 0; j < 4; ++j) {
                    int xv = xi[j][i];
                    acc[j][0] = __dp4a(xv, ea.x, acc[j][0]);
                    acc[j][1] = __dp4a(xv, ea.y, acc[j][1]);
                    acc[j][2] = __dp4a(xv, ea.z, acc[j][2]);
                    acc[j][3] = __dp4a(xv, ea.w, acc[j][3]);
                    acc[j][4] = __dp4a(xv, eb.x, acc[j][4]);
                    acc[j][5] = __dp4a(xv, eb.y, acc[j][5]);
                    acc[j][6] = __dp4a(xv, eb.z, acc[j][6]);
                    acc[j][7] = __dp4a(xv, eb.w, acc[j][7]);
                }
            }
#pragma unroll
            for (int p = 0; p < 8; ++p) {
                float2 e2 = ef[c8*8 + p];
                int k = q*256 + c8*8 + p;
#pragma unroll
                for (int j = 0; j < 4; ++j) {
                    float f = (float)acc[j][p];
                    float d8 = fmaf(-f * e2.y, xsc[j], e2.x);
                    if (d8 < t3f[j]) {
                        ins4(t[j], packdk(d8, k));
                        t3f[j] = unpd(t[j][3]);
                    }
                }
            }
        }
#pragma unroll
        for (int j = 0; j < 4; ++j)
            g_q[q][rown[j]] = make_uint4(t[j][0], t[j][1], t[j][2], t[j][3]);

        if (tid == 0) ms[0] = atomicAdd(&g_ctr, 1);
        __syncthreads();
        u = ms[0];
    }
}

// ---------- fin: certified merge/rescue + outputs --------------------------
__global__ __launch_bounds__(256) void vq_fin(const float* __restrict__ x,
                                              const float* __restrict__ cb,
                                              float* __restrict__ out) {
    __shared__ float xsw[8][64];
    __shared__ float red[256];
    const int tid = threadIdx.x, lane = tid & 31, wrp = tid >> 5;
    const int n = blockIdx.x*256 + tid;
    const unsigned FULL = 0xffffffffu;

    uint32_t s[16];
#pragma unroll
    for (int q = 0; q < 4; ++q) {
        uint4 v = g_q[q][n];
        s[q*4+0]=v.x; s[q*4+1]=v.y; s[q*4+2]=v.z; s[q*4+3]=v.w;
    }
    float4 xf = g_xf[n];
    float sx = xf.z, B = xf.y;
    float dmin = 3e38f;
#pragma unroll
    for (int i = 0; i < 16; ++i) dmin = fminf(dmin, unpd(s[i]));
    float thresh = dmin + B;
    int ovf = 0;
#pragma unroll
    for (int q = 0; q < 4; ++q) ovf |= (unpd(s[q*4+3]) <= thresh);

    const int b = n >> 12, hw = n & 4095;
    const float* xr = x + (size_t)b*262144 + hw;

    float bestd = 3e38f; int bestk = KCODES;
    if (!ovf) {
#pragma unroll 1
        for (int i = 0; i < 16; ++i) {
            if (unpd(s[i]) > thresh) continue;
            int k = (int)(s[i] & 1023u);
            const float* e = cb + k*DIM;
            float P = 0.f;
#pragma unroll
            for (int c = 0; c < DIM; ++c) P = fmaf(xr[c*4096], e[c], P);
            float d = __fadd_rn(__fadd_rn(sx, g_ef[k].x), __fmul_rn(-2.0f, P));
            if (d < bestd || (d == bestd && k < bestk)) { bestd = d; bestk = k; }
        }
    }
    // overflow rows: full exact scan, warp-cooperative (R6-verified pattern)
    unsigned m = __ballot_sync(FULL, ovf);
    while (m) {
        int src = __ffs(m)-1; m &= m-1;
        int rn = __shfl_sync(FULL, n, src);
        int bb = rn>>12, hh = rn&4095;
        const float* xr2 = x + (size_t)bb*262144 + hh;
        for (int c = lane; c < 64; c += 32) xsw[wrp][c] = xr2[c*4096];
        __syncwarp();
        float sxr = 0.f;
#pragma unroll
        for (int c = 0; c < 64; ++c) sxr = fmaf(xsw[wrp][c], xsw[wrp][c], sxr);
        float bd = 3e38f; int bk = 0;
        for (int k0 = 0; k0 < 32; ++k0) {
            int k = lane*32 + k0;
            const float* e = cb + k*64;
            float P = 0.f;
#pragma unroll
            for (int c = 0; c < 64; ++c) P = fmaf(xsw[wrp][c], e[c], P);
            float d = __fadd_rn(__fadd_rn(sxr, g_ef[k].x), __fmul_rn(-2.0f, P));
            if (d < bd) { bd = d; bk = k; }
        }
#pragma unroll
        for (int o = 16; o > 0; o >>= 1) {
            float dv = __shfl_down_sync(FULL, bd, o);
            int   kv = __shfl_down_sync(FULL, bk, o);
            if (dv < bd || (dv == bd && kv < bk)) { bd = dv; bk = kv; }
        }
        int win = __shfl_sync(FULL, bk, 0);
        if (lane == src) bestk = win;
        __syncwarp();
    }

    const float* e = cb + bestk*DIM;
    float* qo = out + 1 + (size_t)b*262144 + hw;
    float lsum = 0.f;
#pragma unroll
    for (int c = 0; c < DIM; ++c) {
        float ec = __ldg(e + c);
        float d = ec - xr[c*4096];
        lsum = fmaf(d, d, lsum);
        qo[c*4096] = ec;
    }
    out[1 + QELEMS + n] = (float)bestk;

    red[tid] = lsum;
    __syncthreads();
#pragma unroll
    for (int sft = 128; sft > 0; sft >>= 1) {
        if (tid < sft) red[tid] += red[tid + sft];
        __syncthreads();
    }
    if (tid == 0) g_losspart[blockIdx.x] = red[0];
}

__global__ void vq_loss(float* __restrict__ out) {
    __shared__ float red[512];
    int tid = threadIdx.x;
    red[tid] = g_losspart[tid];
    __syncthreads();
    for (int sft = 256; sft > 0; sft >>= 1) {
        if (tid < sft) red[tid] += red[tid + sft];
        __syncthreads();
    }
    if (tid == 0) out[0] = red[0] * (1.25f / (float)QELEMS);
}

extern "C" void kernel_launch(void* const* d_in, const int* in_sizes, int n_in,
                              void* d_out, int out_size) {
    const float* x  = (const float*)d_in[0];
    const float* cb = (const float*)d_in[1];
    float* out = (float*)d_out;
    vq_prep<<<4, 256>>>(cb);
    vq_xq<<<NROWS/128, 128>>>(x);
    vq_main<<<NSM, 128>>>();
    vq_fin<<<NROWS/256, 256>>>(x, cb, out);
    vq_loss<<<1, 512>>>(out);
}